// round 2
// baseline (speedup 1.0000x reference)
#include <cuda_runtime.h>
#include <cuda_bf16.h>

#define LATENT 128
#define BN 64
#define MAXN 100352

// Scratch accumulators (allocation-free: __device__ globals)
__device__ float g_force[MAXN * 3];
__device__ float g_torque[MAXN * 3];
__device__ float g_cons[MAXN * 3];
__device__ float g_count[MAXN];

struct NodeArgs {
    const float* latent;
    const float* vel;
    const float* W1[4];
    const float* b1[4];
    const float* W2[4];
    const float* b2[4];
    float* out;
    int N;
};

__global__ void zero_kernel(int N) {
    int i = blockIdx.x * blockDim.x + threadIdx.x;
    int n3 = N * 3;
    if (i < n3) {
        g_force[i] = 0.f;
        g_torque[i] = 0.f;
        g_cons[i] = 0.f;
    }
    if (i < N) g_count[i] = 0.f;
}

__global__ __launch_bounds__(512) void edge_kernel(const int* __restrict__ recv,
                                                   const float* __restrict__ f,
                                                   const float* __restrict__ t,
                                                   const float* __restrict__ c,
                                                   int E) {
    int stride = gridDim.x * blockDim.x;
    for (int e = blockIdx.x * blockDim.x + threadIdx.x; e < E; e += stride) {
        int r = __ldg(&recv[e]);
        int e3 = 3 * e;
        int r3 = 3 * r;
        float f0 = __ldg(&f[e3 + 0]);
        float f1 = __ldg(&f[e3 + 1]);
        float f2 = __ldg(&f[e3 + 2]);
        float t0 = __ldg(&t[e3 + 0]);
        float t1 = __ldg(&t[e3 + 1]);
        float t2 = __ldg(&t[e3 + 2]);
        float c0 = __ldg(&c[e3 + 0]);
        float c1 = __ldg(&c[e3 + 1]);
        float c2 = __ldg(&c[e3 + 2]);
        atomicAdd(&g_force[r3 + 0], f0);
        atomicAdd(&g_force[r3 + 1], f1);
        atomicAdd(&g_force[r3 + 2], f2);
        atomicAdd(&g_torque[r3 + 0], t0);
        atomicAdd(&g_torque[r3 + 1], t1);
        atomicAdd(&g_torque[r3 + 2], t2);
        atomicAdd(&g_cons[r3 + 0], c0);
        atomicAdd(&g_cons[r3 + 1], c1);
        atomicAdd(&g_cons[r3 + 2], c2);
        atomicAdd(&g_count[r], 1.0f);
    }
}

// Shared memory layout (floats):
//  xs   : BN x 132 (padded rows)          [0,      8448)
//  ws   : 128 x 128                       [8448,  24832)
//  b1s  : 128                             [24832, 24960)
//  w2s  : 128*3                           [24960, 25344)
//  b2s  : 4                               [25344, 25348)
//  outs : BN x 6                          [25348, 25732)
#define SMEM_FLOATS 25732
#define XS_OFF   0
#define WS_OFF   8448
#define B1_OFF   24832
#define W2_OFF   24960
#define B2_OFF   25344
#define OUT_OFF  25348
#define XS_STRIDE 132

__global__ __launch_bounds__(256, 2) void node_kernel(NodeArgs args) {
    extern __shared__ float smem[];
    float* xs   = smem + XS_OFF;
    float* ws   = smem + WS_OFF;
    float* b1s  = smem + B1_OFF;
    float* w2s  = smem + W2_OFF;
    float* b2s  = smem + B2_OFF;
    float* outs = smem + OUT_OFF;

    const int tid = threadIdx.x;
    const int jg = tid & 15;    // hidden group: j in [jg*8, jg*8+8)
    const int ng = tid >> 4;    // node group : n in [ng*4, ng*4+4)
    const int base = blockIdx.x * BN;
    const int N = args.N;

    // Load x tile (BN x 128), zero-padded past N
    const float4* lat4 = (const float4*)args.latent;
    for (int i = tid; i < BN * (LATENT / 4); i += 256) {
        int n = i >> 5;
        int k4 = i & 31;
        float4 v = make_float4(0.f, 0.f, 0.f, 0.f);
        int gn = base + n;
        if (gn < N) v = lat4[gn * (LATENT / 4) + k4];
        *(float4*)&xs[n * XS_STRIDE + k4 * 4] = v;
    }

    for (int m = 0; m < 4; m++) {
        __syncthreads();  // ws reuse hazard from previous iteration

        // Stage W1, b1, W2, b2 for this MLP
        const float4* w14 = (const float4*)args.W1[m];
        for (int i = tid; i < 4096; i += 256) ((float4*)ws)[i] = w14[i];
        if (tid < 128) b1s[tid] = args.b1[m][tid];
        const int od = (m == 2) ? 3 : 1;
        for (int i = tid; i < 128 * od; i += 256) w2s[i] = args.W2[m][i];
        if (tid < od) b2s[tid] = args.b2[m][tid];
        __syncthreads();

        // First layer: acc[nv][jj] = sum_k x[n][k] * W1[k][j]
        float acc[4][8];
        #pragma unroll
        for (int nv = 0; nv < 4; nv++)
            #pragma unroll
            for (int jj = 0; jj < 8; jj++) acc[nv][jj] = 0.f;

        #pragma unroll 8
        for (int k = 0; k < 128; k++) {
            float4 w0 = *(const float4*)&ws[k * 128 + jg * 8];
            float4 w1 = *(const float4*)&ws[k * 128 + jg * 8 + 4];
            #pragma unroll
            for (int nv = 0; nv < 4; nv++) {
                float xv = xs[(ng * 4 + nv) * XS_STRIDE + k];
                acc[nv][0] += xv * w0.x;
                acc[nv][1] += xv * w0.y;
                acc[nv][2] += xv * w0.z;
                acc[nv][3] += xv * w0.w;
                acc[nv][4] += xv * w1.x;
                acc[nv][5] += xv * w1.y;
                acc[nv][6] += xv * w1.z;
                acc[nv][7] += xv * w1.w;
            }
        }

        // ReLU + second layer (partial over this thread's 8 hidden units),
        // then butterfly-reduce over the 16 jg lanes.
        const int off = (m == 0) ? 0 : (m == 1) ? 1 : (m == 2) ? 2 : 5;
        #pragma unroll
        for (int nv = 0; nv < 4; nv++) {
            float h[8];
            #pragma unroll
            for (int jj = 0; jj < 8; jj++)
                h[jj] = fmaxf(acc[nv][jj] + b1s[jg * 8 + jj], 0.f);
            for (int o = 0; o < od; o++) {
                float p = 0.f;
                #pragma unroll
                for (int jj = 0; jj < 8; jj++)
                    p += h[jj] * w2s[(jg * 8 + jj) * od + o];
                p += __shfl_xor_sync(0xffffffffu, p, 8);
                p += __shfl_xor_sync(0xffffffffu, p, 4);
                p += __shfl_xor_sync(0xffffffffu, p, 2);
                p += __shfl_xor_sync(0xffffffffu, p, 1);
                if (jg == 0)
                    outs[(ng * 4 + nv) * 6 + off + o] = p + b2s[o];
            }
        }
    }

    __syncthreads();

    // Final combine: one thread per node
    if (tid < BN) {
        int gn = base + tid;
        if (gn < N) {
            float im = outs[tid * 6 + 0];
            float ii = outs[tid * 6 + 1];
            float ex = outs[tid * 6 + 2];
            float ey = outs[tid * 6 + 3];
            float ez = outs[tid * 6 + 4];
            float vs = outs[tid * 6 + 5];
            float cnt = fmaxf(g_count[gn], 1.0f);
            int b = gn * 3;
            int N3 = N * 3;
            float* out = args.out;
            // delta_velocity
            out[b + 0] = im * g_force[b + 0];
            out[b + 1] = im * g_force[b + 1];
            out[b + 2] = im * g_force[b + 2];
            // delta_angular_velocity
            out[N3 + b + 0] = ii * g_torque[b + 0];
            out[N3 + b + 1] = ii * g_torque[b + 1];
            out[N3 + b + 2] = ii * g_torque[b + 2];
            // displacement
            const float* vel = args.vel;
            out[2 * N3 + b + 0] = (vel[b + 0] + ex) * vs + g_cons[b + 0] / cnt;
            out[2 * N3 + b + 1] = (vel[b + 1] + ey) * vs + g_cons[b + 1] / cnt;
            out[2 * N3 + b + 2] = (vel[b + 2] + ez) * vs + g_cons[b + 2] / cnt;
        }
    }
}

extern "C" void kernel_launch(void* const* d_in, const int* in_sizes, int n_in,
                              void* d_out, int out_size) {
    const int* ei            = (const int*)d_in[0];     // [2, E] int32
    const float* latent      = (const float*)d_in[1];   // [N, 128]
    const float* vel         = (const float*)d_in[2];   // [N, 3]
    const float* ef          = (const float*)d_in[3];   // [E, 3]
    const float* et          = (const float*)d_in[4];   // [E, 3]
    const float* ec          = (const float*)d_in[5];   // [E, 3]

    const int E = in_sizes[0] / 2;
    const int N = in_sizes[1] / LATENT;

    NodeArgs a;
    a.latent = latent;
    a.vel = vel;
    // order: m (6..9), i (10..13), e (14..17), v (18..21)
    for (int m = 0; m < 4; m++) {
        a.W1[m] = (const float*)d_in[6 + 4 * m + 0];
        a.b1[m] = (const float*)d_in[6 + 4 * m + 1];
        a.W2[m] = (const float*)d_in[6 + 4 * m + 2];
        a.b2[m] = (const float*)d_in[6 + 4 * m + 3];
    }
    a.out = (float*)d_out;
    a.N = N;

    const int smem_bytes = SMEM_FLOATS * 4;
    // Persistent function attribute; non-stream API, capture-safe.
    (void)cudaFuncSetAttribute(node_kernel,
                               cudaFuncAttributeMaxDynamicSharedMemorySize,
                               smem_bytes);

    zero_kernel<<<(N * 3 + 255) / 256, 256>>>(N);
    edge_kernel<<<1184, 512>>>(ei + E, ef, et, ec, E);
    node_kernel<<<(N + BN - 1) / BN, 256, smem_bytes>>>(a);
}

// round 3
// speedup vs baseline: 1.0870x; 1.0870x over previous
#include <cuda_runtime.h>
#include <cuda_bf16.h>

#define LATENT 128
#define BN 64
#define MAXN 100352
#define RATIO 10   // node blocks per edge block

// Scratch (allocation-free: __device__ globals)
__device__ float g_force[MAXN * 3];
__device__ float g_torque[MAXN * 3];
__device__ float g_cons[MAXN * 3];
__device__ float g_count[MAXN];
__device__ float g_mlp[MAXN * 6];
__device__ unsigned int g_ctr;

struct FusedArgs {
    const float* latent;
    const float* W1[4];
    const float* b1[4];
    const float* W2[4];
    const float* b2[4];
    const int* recv;
    const float* ef;
    const float* et;
    const float* ec;
    int N;
    int E;
    int NB;        // node block count
    int smallgrid; // 1 -> edge block is bid==NB
};

__global__ void zero_kernel(int N) {
    int i = blockIdx.x * blockDim.x + threadIdx.x;
    int n3 = N * 3;
    if (i < n3) {
        g_force[i] = 0.f;
        g_torque[i] = 0.f;
        g_cons[i] = 0.f;
    }
    if (i < N) g_count[i] = 0.f;
    if (i == 0) g_ctr = 0u;
}

// Shared memory layout (floats):
//  xs  : 128 x 68 (k-major, padded)   [0,     8704)
//  ws  : 128 x 128                    [8704,  25088)
//  b1s : 128                          [25088, 25216)
//  w2s : 128*3                        [25216, 25600)
//  b2s : 4                            [25600, 25604)
#define SMEM_FLOATS 25604
#define XS_OFF 0
#define WS_OFF 8704
#define B1_OFF 25088
#define W2_OFF 25216
#define B2_OFF 25600
#define XS_STRIDE 68

__device__ __forceinline__ void edge_scalar(const FusedArgs& a, int e) {
    int r = __ldg(&a.recv[e]);
    int e3 = 3 * e, r3 = 3 * r;
    atomicAdd(&g_force[r3 + 0], __ldg(&a.ef[e3 + 0]));
    atomicAdd(&g_force[r3 + 1], __ldg(&a.ef[e3 + 1]));
    atomicAdd(&g_force[r3 + 2], __ldg(&a.ef[e3 + 2]));
    atomicAdd(&g_torque[r3 + 0], __ldg(&a.et[e3 + 0]));
    atomicAdd(&g_torque[r3 + 1], __ldg(&a.et[e3 + 1]));
    atomicAdd(&g_torque[r3 + 2], __ldg(&a.et[e3 + 2]));
    atomicAdd(&g_cons[r3 + 0], __ldg(&a.ec[e3 + 0]));
    atomicAdd(&g_cons[r3 + 1], __ldg(&a.ec[e3 + 1]));
    atomicAdd(&g_cons[r3 + 2], __ldg(&a.ec[e3 + 2]));
    atomicAdd(&g_count[r], 1.0f);
}

__device__ __forceinline__ void edge3(int r, float x, float y, float z,
                                      float tx, float ty, float tz,
                                      float cx, float cy, float cz) {
    int r3 = 3 * r;
    atomicAdd(&g_force[r3 + 0], x);
    atomicAdd(&g_force[r3 + 1], y);
    atomicAdd(&g_force[r3 + 2], z);
    atomicAdd(&g_torque[r3 + 0], tx);
    atomicAdd(&g_torque[r3 + 1], ty);
    atomicAdd(&g_torque[r3 + 2], tz);
    atomicAdd(&g_cons[r3 + 0], cx);
    atomicAdd(&g_cons[r3 + 1], cy);
    atomicAdd(&g_cons[r3 + 2], cz);
    atomicAdd(&g_count[r], 1.0f);
}

__global__ __launch_bounds__(256) void fused_kernel(FusedArgs args) {
    const int bid = blockIdx.x;
    const int tid = threadIdx.x;
    bool is_edge;
    int nbid;
    if (args.smallgrid) {
        is_edge = (bid == args.NB);
        nbid = bid;
    } else {
        int m = bid % (RATIO + 1);
        is_edge = (m == RATIO);
        nbid = (bid / (RATIO + 1)) * RATIO + m;
    }

    if (is_edge) {
        // ---------- EDGE ROLE: work-stealing, 4-edge vectorized chunks ----------
        const int E = args.E;
        const int tail = E & 3;
        const int C = E >> 2;
        // scalar tail: handled once, by the first edge block
        bool first_edge = args.smallgrid ? true : (bid / (RATIO + 1) == 0);
        if (first_edge && tid < tail) edge_scalar(args, (C << 2) + tid);

        const int4* r4p = (const int4*)args.recv;
        const float4* f4 = (const float4*)args.ef;
        const float4* t4 = (const float4*)args.et;
        const float4* c4 = (const float4*)args.ec;

        __shared__ unsigned int s_base;
        for (;;) {
            __syncthreads();
            if (tid == 0) s_base = atomicAdd(&g_ctr, 256u);
            __syncthreads();
            unsigned int base = s_base;
            if (base >= (unsigned)C) break;
            unsigned int ch = base + tid;
            if (ch < (unsigned)C) {
                int4 r = __ldg(&r4p[ch]);
                float4 a0 = __ldg(&f4[3 * ch + 0]);
                float4 a1 = __ldg(&f4[3 * ch + 1]);
                float4 a2 = __ldg(&f4[3 * ch + 2]);
                float4 b0 = __ldg(&t4[3 * ch + 0]);
                float4 b1 = __ldg(&t4[3 * ch + 1]);
                float4 b2 = __ldg(&t4[3 * ch + 2]);
                float4 c0 = __ldg(&c4[3 * ch + 0]);
                float4 c1 = __ldg(&c4[3 * ch + 1]);
                float4 c2 = __ldg(&c4[3 * ch + 2]);
                edge3(r.x, a0.x, a0.y, a0.z, b0.x, b0.y, b0.z, c0.x, c0.y, c0.z);
                edge3(r.y, a0.w, a1.x, a1.y, b0.w, b1.x, b1.y, c0.w, c1.x, c1.y);
                edge3(r.z, a1.z, a1.w, a2.x, b1.z, b1.w, b2.x, c1.z, c1.w, c2.x);
                edge3(r.w, a2.y, a2.z, a2.w, b2.y, b2.z, b2.w, c2.y, c2.z, c2.w);
            }
        }
        return;
    }

    // ---------- NODE ROLE: 4 fused 2-layer MLPs over a 64-node tile ----------
    extern __shared__ float smem[];
    float* xs  = smem + XS_OFF;
    float* ws  = smem + WS_OFF;
    float* b1s = smem + B1_OFF;
    float* w2s = smem + W2_OFF;
    float* b2s = smem + B2_OFF;

    const int jg = tid & 15;   // hidden group: j in [jg*8, jg*8+8)
    const int ng = tid >> 4;   // node group : n in [ng*4, ng*4+4)
    const int base = nbid * BN;
    const int N = args.N;

    // Load x tile transposed: xs[k][n], zero-padded past N
    const float4* lat4 = (const float4*)args.latent;
    for (int i = tid; i < BN * (LATENT / 4); i += 256) {
        int n = i >> 5;
        int k4 = i & 31;
        float4 v = make_float4(0.f, 0.f, 0.f, 0.f);
        int gn = base + n;
        if (gn < N) v = lat4[gn * (LATENT / 4) + k4];
        xs[(4 * k4 + 0) * XS_STRIDE + n] = v.x;
        xs[(4 * k4 + 1) * XS_STRIDE + n] = v.y;
        xs[(4 * k4 + 2) * XS_STRIDE + n] = v.z;
        xs[(4 * k4 + 3) * XS_STRIDE + n] = v.w;
    }

    for (int m = 0; m < 4; m++) {
        __syncthreads();  // ws reuse hazard from previous iteration / xs ready

        const float4* w14 = (const float4*)args.W1[m];
        for (int i = tid; i < 4096; i += 256) ((float4*)ws)[i] = w14[i];
        if (tid < 128) b1s[tid] = args.b1[m][tid];
        const int od = (m == 2) ? 3 : 1;
        for (int i = tid; i < 128 * od; i += 256) w2s[i] = args.W2[m][i];
        if (tid < od) b2s[tid] = args.b2[m][tid];
        __syncthreads();

        float acc[4][8];
        #pragma unroll
        for (int nv = 0; nv < 4; nv++)
            #pragma unroll
            for (int jj = 0; jj < 8; jj++) acc[nv][jj] = 0.f;

        #pragma unroll 4
        for (int k = 0; k < 128; k++) {
            float4 w0 = *(const float4*)&ws[k * 128 + jg * 8];
            float4 w1 = *(const float4*)&ws[k * 128 + jg * 8 + 4];
            float4 xv = *(const float4*)&xs[k * XS_STRIDE + ng * 4];
            const float xa[4] = {xv.x, xv.y, xv.z, xv.w};
            #pragma unroll
            for (int nv = 0; nv < 4; nv++) {
                float x = xa[nv];
                acc[nv][0] += x * w0.x;
                acc[nv][1] += x * w0.y;
                acc[nv][2] += x * w0.z;
                acc[nv][3] += x * w0.w;
                acc[nv][4] += x * w1.x;
                acc[nv][5] += x * w1.y;
                acc[nv][6] += x * w1.z;
                acc[nv][7] += x * w1.w;
            }
        }

        // ReLU + second layer partials; butterfly-reduce over the 16 jg lanes
        const int off = (m == 0) ? 0 : (m == 1) ? 1 : (m == 2) ? 2 : 5;
        #pragma unroll
        for (int nv = 0; nv < 4; nv++) {
            float h[8];
            #pragma unroll
            for (int jj = 0; jj < 8; jj++)
                h[jj] = fmaxf(acc[nv][jj] + b1s[jg * 8 + jj], 0.f);
            for (int o = 0; o < od; o++) {
                float p = 0.f;
                #pragma unroll
                for (int jj = 0; jj < 8; jj++)
                    p += h[jj] * w2s[(jg * 8 + jj) * od + o];
                p += __shfl_xor_sync(0xffffffffu, p, 8);
                p += __shfl_xor_sync(0xffffffffu, p, 4);
                p += __shfl_xor_sync(0xffffffffu, p, 2);
                p += __shfl_xor_sync(0xffffffffu, p, 1);
                if (jg == 0) {
                    int gn = base + ng * 4 + nv;
                    if (gn < N) g_mlp[gn * 6 + off + o] = p + b2s[o];
                }
            }
        }
    }
}

__global__ void combine_kernel(const float* __restrict__ vel,
                               float* __restrict__ out, int N) {
    int n = blockIdx.x * blockDim.x + threadIdx.x;
    if (n >= N) return;
    float im = g_mlp[n * 6 + 0];
    float ii = g_mlp[n * 6 + 1];
    float ex = g_mlp[n * 6 + 2];
    float ey = g_mlp[n * 6 + 3];
    float ez = g_mlp[n * 6 + 4];
    float vs = g_mlp[n * 6 + 5];
    float cnt = fmaxf(g_count[n], 1.0f);
    int b = n * 3;
    int N3 = N * 3;
    out[b + 0] = im * g_force[b + 0];
    out[b + 1] = im * g_force[b + 1];
    out[b + 2] = im * g_force[b + 2];
    out[N3 + b + 0] = ii * g_torque[b + 0];
    out[N3 + b + 1] = ii * g_torque[b + 1];
    out[N3 + b + 2] = ii * g_torque[b + 2];
    out[2 * N3 + b + 0] = (vel[b + 0] + ex) * vs + g_cons[b + 0] / cnt;
    out[2 * N3 + b + 1] = (vel[b + 1] + ey) * vs + g_cons[b + 1] / cnt;
    out[2 * N3 + b + 2] = (vel[b + 2] + ez) * vs + g_cons[b + 2] / cnt;
}

extern "C" void kernel_launch(void* const* d_in, const int* in_sizes, int n_in,
                              void* d_out, int out_size) {
    const int* ei       = (const int*)d_in[0];     // [2, E] int32
    const float* latent = (const float*)d_in[1];   // [N, 128]
    const float* vel    = (const float*)d_in[2];   // [N, 3]
    const float* ef     = (const float*)d_in[3];   // [E, 3]
    const float* et     = (const float*)d_in[4];   // [E, 3]
    const float* ec     = (const float*)d_in[5];   // [E, 3]

    const int E = in_sizes[0] / 2;
    const int N = in_sizes[1] / LATENT;

    FusedArgs a;
    a.latent = latent;
    for (int m = 0; m < 4; m++) {
        a.W1[m] = (const float*)d_in[6 + 4 * m + 0];
        a.b1[m] = (const float*)d_in[6 + 4 * m + 1];
        a.W2[m] = (const float*)d_in[6 + 4 * m + 2];
        a.b2[m] = (const float*)d_in[6 + 4 * m + 3];
    }
    a.recv = ei + E;  // receivers = edge_index[1]
    a.ef = ef;
    a.et = et;
    a.ec = ec;
    a.N = N;
    a.E = E;

    int NB = (N + BN - 1) / BN;
    int EB = NB / RATIO;
    int total;
    if (EB == 0) {
        a.smallgrid = 1;
        total = NB + 1;
    } else {
        a.smallgrid = 0;
        total = NB + EB;
    }
    a.NB = NB;

    const int smem_bytes = SMEM_FLOATS * 4;
    (void)cudaFuncSetAttribute(fused_kernel,
                               cudaFuncAttributeMaxDynamicSharedMemorySize,
                               smem_bytes);

    zero_kernel<<<(N * 3 + 255) / 256, 256>>>(N);
    fused_kernel<<<total, 256, smem_bytes>>>(a);
    combine_kernel<<<(N + 255) / 256, 256>>>(vel, (float*)d_out, N);
}

// round 8
// speedup vs baseline: 3.8802x; 3.5696x over previous
#include <cuda_runtime.h>
#include <cuda_bf16.h>
#include <cstdint>

#define LATENT 128
#define MAXN 100352
#define TN 128            // nodes per tile

// ---------------- device globals (allocation-free scratch) ----------------
__device__ __align__(16) float g_force4[MAXN * 4];   // .w = count
__device__ __align__(16) float g_torque4[MAXN * 4];
__device__ __align__(16) float g_cons4[MAXN * 4];
__device__ float g_mlp[MAXN * 6];
__device__ unsigned int g_ctr;
// W1 per MLP in mma B-fragment word layout: [0,8192) hi words, [8192,16384) lo words
__device__ __align__(16) uint32_t g_wb[4][16384];

// ---------------- helpers ----------------
__device__ __forceinline__ void mma16816(float* c, const uint32_t* a, uint32_t b0, uint32_t b1) {
    asm volatile(
        "mma.sync.aligned.m16n8k16.row.col.f32.bf16.bf16.f32 "
        "{%0,%1,%2,%3}, {%4,%5,%6,%7}, {%8,%9}, {%0,%1,%2,%3};"
        : "+f"(c[0]), "+f"(c[1]), "+f"(c[2]), "+f"(c[3])
        : "r"(a[0]), "r"(a[1]), "r"(a[2]), "r"(a[3]), "r"(b0), "r"(b1));
}

__device__ __forceinline__ void redv4(float* p, float a, float b, float c, float d) {
    asm volatile("red.global.add.v4.f32 [%0], {%1, %2, %3, %4};"
                 :: "l"(p), "f"(a), "f"(b), "f"(c), "f"(d) : "memory");
}

__device__ __forceinline__ void split_pack(float2 v, uint32_t& hw, uint32_t& lw) {
    __nv_bfloat16 h0 = __float2bfloat16(v.x);
    __nv_bfloat16 h1 = __float2bfloat16(v.y);
    __nv_bfloat16 l0 = __float2bfloat16(v.x - __bfloat162float(h0));
    __nv_bfloat16 l1 = __float2bfloat16(v.y - __bfloat162float(h1));
    __nv_bfloat162 hp; hp.x = h0; hp.y = h1;
    __nv_bfloat162 lp; lp.x = l0; lp.y = l1;
    hw = *(uint32_t*)&hp;
    lw = *(uint32_t*)&lp;
}

// ---------------- small kernels ----------------
__global__ void zero_kernel(int N) {
    int i = blockIdx.x * blockDim.x + threadIdx.x;
    int n4 = N * 4;
    if (i < n4) { g_force4[i] = 0.f; g_torque4[i] = 0.f; g_cons4[i] = 0.f; }
    if (i == 0) g_ctr = 0u;
}

struct PrepArgs { const float* W1[4]; };

// B-fragment layout: word idx r = ((nb*8+kb)*32 + lane)*2 + w
// lane: tig=lane&3, gid=lane>>2 ; k = kb*16 + tig*2 + w*8 ; n = nb*8 + gid
// word = bf16x2( W1[k][n], W1[k+1][n] )   (W1 row-major [k][n], 128x128)
__global__ void prep_w_kernel(PrepArgs a) {
    int idx = blockIdx.x * blockDim.x + threadIdx.x;   // 4 * 8192
    if (idx >= 4 * 8192) return;
    int m = idx >> 13;
    int r = idx & 8191;
    int w    = r & 1;
    int lane = (r >> 1) & 31;
    int kb   = (r >> 6) & 7;
    int nb   = r >> 9;
    int tig = lane & 3, gid = lane >> 2;
    int k = kb * 16 + tig * 2 + w * 8;
    int n = nb * 8 + gid;
    const float* W = a.W1[m];
    float2 v = make_float2(W[k * 128 + n], W[(k + 1) * 128 + n]);
    uint32_t hw, lw;
    split_pack(v, hw, lw);
    g_wb[m][r] = hw;
    g_wb[m][8192 + r] = lw;
}

// ---------------- fused kernel ----------------
struct FusedArgs {
    const float* latent;
    const float* b1[4];
    const float* W2[4];
    const float* b2[4];
    const int* recv;
    const float* ef;
    const float* et;
    const float* ec;
    int N, NB, E;
};

// smem: wbuf 65536 B | b1s 2048 B | w2s 3072 B | b2s 24 B
#define SM_B1   65536
#define SM_W2   67584
#define SM_B2   70656
#define SMEM_BYTES 70784

__device__ __constant__ int c_w2off[4] = {0, 128, 256, 640};
__device__ __constant__ int c_od[4]    = {1, 1, 3, 1};
__device__ __constant__ int c_oout[4]  = {0, 1, 2, 5};

__device__ __forceinline__ void edge_scalar_tail(const FusedArgs& a, int e) {
    int r = __ldg(&a.recv[e]);
    int e3 = 3 * e, r4 = 4 * r;
    atomicAdd(&g_force4[r4 + 0], __ldg(&a.ef[e3 + 0]));
    atomicAdd(&g_force4[r4 + 1], __ldg(&a.ef[e3 + 1]));
    atomicAdd(&g_force4[r4 + 2], __ldg(&a.ef[e3 + 2]));
    atomicAdd(&g_force4[r4 + 3], 1.0f);
    atomicAdd(&g_torque4[r4 + 0], __ldg(&a.et[e3 + 0]));
    atomicAdd(&g_torque4[r4 + 1], __ldg(&a.et[e3 + 1]));
    atomicAdd(&g_torque4[r4 + 2], __ldg(&a.et[e3 + 2]));
    atomicAdd(&g_cons4[r4 + 0], __ldg(&a.ec[e3 + 0]));
    atomicAdd(&g_cons4[r4 + 1], __ldg(&a.ec[e3 + 1]));
    atomicAdd(&g_cons4[r4 + 2], __ldg(&a.ec[e3 + 2]));
}

__device__ __forceinline__ void edge1(int r, float fx, float fy, float fz,
                                      float tx, float ty, float tz,
                                      float cx, float cy, float cz) {
    redv4(&g_force4[4 * r], fx, fy, fz, 1.0f);
    redv4(&g_torque4[4 * r], tx, ty, tz, 0.0f);
    redv4(&g_cons4[4 * r], cx, cy, cz, 0.0f);
}

__global__ __launch_bounds__(256, 2) void fused_kernel(FusedArgs args) {
    const int bid = blockIdx.x;
    const int tid = threadIdx.x;
    const bool is_node = ((bid % 3) == 0) && ((bid / 3) < args.NB);

    if (!is_node) {
        // ================= EDGE ROLE: work-stealing, 4-edge chunks =================
        const int E = args.E;
        const int C = E >> 2;
        const int tail = E & 3;
        if (bid == 1 && tid < tail) edge_scalar_tail(args, (C << 2) + tid);

        const int4* r4p = (const int4*)args.recv;
        const float4* f4 = (const float4*)args.ef;
        const float4* t4 = (const float4*)args.et;
        const float4* c4 = (const float4*)args.ec;
        __shared__ unsigned int s_base;
        for (;;) {
            __syncthreads();
            if (tid == 0) s_base = atomicAdd(&g_ctr, 256u);
            __syncthreads();
            unsigned int base = s_base;
            if (base >= (unsigned)C) break;
            unsigned int ch = base + tid;
            if (ch < (unsigned)C) {
                int4 r = __ldg(&r4p[ch]);
                float4 a0 = __ldg(&f4[3 * ch + 0]);
                float4 a1 = __ldg(&f4[3 * ch + 1]);
                float4 a2 = __ldg(&f4[3 * ch + 2]);
                float4 b0 = __ldg(&t4[3 * ch + 0]);
                float4 b1 = __ldg(&t4[3 * ch + 1]);
                float4 b2 = __ldg(&t4[3 * ch + 2]);
                float4 c0 = __ldg(&c4[3 * ch + 0]);
                float4 c1 = __ldg(&c4[3 * ch + 1]);
                float4 c2 = __ldg(&c4[3 * ch + 2]);
                edge1(r.x, a0.x, a0.y, a0.z, b0.x, b0.y, b0.z, c0.x, c0.y, c0.z);
                edge1(r.y, a0.w, a1.x, a1.y, b0.w, b1.x, b1.y, c0.w, c1.x, c1.y);
                edge1(r.z, a1.z, a1.w, a2.x, b1.z, b1.w, b2.x, c1.z, c1.w, c2.x);
                edge1(r.w, a2.y, a2.z, a2.w, b2.y, b2.z, b2.w, c2.y, c2.z, c2.w);
            }
        }
        return;
    }

    // ================= NODE ROLE: mma.sync bf16-split MLPs =================
    extern __shared__ char smem[];
    uint32_t* wbuf = (uint32_t*)smem;
    float* b1s = (float*)(smem + SM_B1);
    float* w2s = (float*)(smem + SM_W2);
    float* b2s = (float*)(smem + SM_B2);

    const int wid = tid >> 5;
    const int lane = tid & 31;
    const int tig = lane & 3;     // thread-in-group (k pairs / cols)
    const int gid = lane >> 2;    // group id (rows / n)
    const int tile = bid / 3;
    const int base = tile * TN;
    const int N = args.N;

    // small tables
    for (int i = tid; i < 512; i += 256) b1s[i] = args.b1[i >> 7][i & 127];
    for (int i = tid; i < 768; i += 256) {
        int m, o;
        if (i < 128)      { m = 0; o = i; }
        else if (i < 256) { m = 1; o = i - 128; }
        else if (i < 640) { m = 2; o = i - 256; }
        else              { m = 3; o = i - 640; }
        w2s[i] = args.W2[m][o];
    }
    if (tid < 6) {
        int m = (tid == 0) ? 0 : (tid == 1) ? 1 : (tid < 5) ? 2 : 3;
        int o = (tid >= 2 && tid < 5) ? tid - 2 : 0;
        b2s[tid] = args.b2[m][o];
    }

    // ---- build A fragments (hi/lo) from global X; warp owns rows [wid*16, wid*16+16) ----
    const int gn0 = base + wid * 16 + gid;      // rows gid and gid+8
    const int gn1 = gn0 + 8;
    const bool v0 = gn0 < N, v1 = gn1 < N;
    const float* x0 = args.latent + (size_t)gn0 * LATENT;
    const float* x1 = args.latent + (size_t)gn1 * LATENT;

    uint32_t ah[32], al[32];
    #pragma unroll
    for (int kb = 0; kb < 8; kb++) {
        const int kc = kb * 16 + tig * 2;
        float2 p00 = v0 ? *(const float2*)(x0 + kc)     : make_float2(0.f, 0.f);
        float2 p01 = v0 ? *(const float2*)(x0 + kc + 8) : make_float2(0.f, 0.f);
        float2 p10 = v1 ? *(const float2*)(x1 + kc)     : make_float2(0.f, 0.f);
        float2 p11 = v1 ? *(const float2*)(x1 + kc + 8) : make_float2(0.f, 0.f);
        split_pack(p00, ah[kb * 4 + 0], al[kb * 4 + 0]);
        split_pack(p10, ah[kb * 4 + 1], al[kb * 4 + 1]);
        split_pack(p01, ah[kb * 4 + 2], al[kb * 4 + 2]);
        split_pack(p11, ah[kb * 4 + 3], al[kb * 4 + 3]);
    }

    for (int m = 0; m < 4; m++) {
        __syncthreads();   // previous iteration's wbuf reads done
        {
            const uint4* src = (const uint4*)&g_wb[m][0];
            uint4* dst = (uint4*)wbuf;
            // front-batched LDGs (4 in flight per thread), then stores
            #pragma unroll 1
            for (int i = tid; i < 4096; i += 1024) {
                uint4 t0 = __ldg(&src[i]);
                uint4 t1 = __ldg(&src[i + 256]);
                uint4 t2 = __ldg(&src[i + 512]);
                uint4 t3 = __ldg(&src[i + 768]);
                dst[i] = t0;
                dst[i + 256] = t1;
                dst[i + 512] = t2;
                dst[i + 768] = t3;
            }
        }
        __syncthreads();   // weights ready

        const int od = c_od[m];
        const int w2o = c_w2off[m];
        const int oo = c_oout[m];
        const float* b1m = b1s + m * 128;
        float pr0[3] = {0.f, 0.f, 0.f};
        float pr1[3] = {0.f, 0.f, 0.f};

        #pragma unroll 2
        for (int nb = 0; nb < 16; nb++) {
            float acc[4] = {0.f, 0.f, 0.f, 0.f};
            #pragma unroll
            for (int kb = 0; kb < 8; kb++) {
                const int wi = (nb * 8 + kb) * 64 + lane * 2;
                uint2 bh = *(const uint2*)&wbuf[wi];
                uint2 bl = *(const uint2*)&wbuf[8192 + wi];
                mma16816(acc, &ah[kb * 4], bh.x, bh.y);
                mma16816(acc, &al[kb * 4], bh.x, bh.y);
                mma16816(acc, &ah[kb * 4], bl.x, bl.y);
            }
            const int col0 = nb * 8 + tig * 2;
            const int col1 = col0 + 1;
            float h0 = fmaxf(acc[0] + b1m[col0], 0.f);
            float h1 = fmaxf(acc[1] + b1m[col1], 0.f);
            float h2 = fmaxf(acc[2] + b1m[col0], 0.f);
            float h3 = fmaxf(acc[3] + b1m[col1], 0.f);
            if (od == 1) {
                pr0[0] += h0 * w2s[w2o + col0] + h1 * w2s[w2o + col1];
                pr1[0] += h2 * w2s[w2o + col0] + h3 * w2s[w2o + col1];
            } else {
                #pragma unroll
                for (int o = 0; o < 3; o++) {
                    pr0[o] += h0 * w2s[w2o + col0 * 3 + o] + h1 * w2s[w2o + col1 * 3 + o];
                    pr1[o] += h2 * w2s[w2o + col0 * 3 + o] + h3 * w2s[w2o + col1 * 3 + o];
                }
            }
        }

        // reduce across the 4 lanes of each row group (tig bits 0,1)
        #pragma unroll
        for (int o = 0; o < 3; o++) {
            pr0[o] += __shfl_xor_sync(0xffffffffu, pr0[o], 1);
            pr0[o] += __shfl_xor_sync(0xffffffffu, pr0[o], 2);
            pr1[o] += __shfl_xor_sync(0xffffffffu, pr1[o], 1);
            pr1[o] += __shfl_xor_sync(0xffffffffu, pr1[o], 2);
        }
        if (tig == 0) {
            if (v0) {
                g_mlp[gn0 * 6 + oo] = pr0[0] + b2s[oo];
                if (od == 3) {
                    g_mlp[gn0 * 6 + 3] = pr0[1] + b2s[3];
                    g_mlp[gn0 * 6 + 4] = pr0[2] + b2s[4];
                }
            }
            if (v1) {
                g_mlp[gn1 * 6 + oo] = pr1[0] + b2s[oo];
                if (od == 3) {
                    g_mlp[gn1 * 6 + 3] = pr1[1] + b2s[3];
                    g_mlp[gn1 * 6 + 4] = pr1[2] + b2s[4];
                }
            }
        }
    }
}

// ---------------- combine ----------------
__global__ void combine_kernel(const float* __restrict__ vel,
                               float* __restrict__ out, int N) {
    int n = blockIdx.x * blockDim.x + threadIdx.x;
    if (n >= N) return;
    float im = g_mlp[n * 6 + 0];
    float ii = g_mlp[n * 6 + 1];
    float ex = g_mlp[n * 6 + 2];
    float ey = g_mlp[n * 6 + 3];
    float ez = g_mlp[n * 6 + 4];
    float vs = g_mlp[n * 6 + 5];
    int p = n * 4;
    float cnt = fmaxf(g_force4[p + 3], 1.0f);
    int b = n * 3;
    int N3 = N * 3;
    out[b + 0] = im * g_force4[p + 0];
    out[b + 1] = im * g_force4[p + 1];
    out[b + 2] = im * g_force4[p + 2];
    out[N3 + b + 0] = ii * g_torque4[p + 0];
    out[N3 + b + 1] = ii * g_torque4[p + 1];
    out[N3 + b + 2] = ii * g_torque4[p + 2];
    out[2 * N3 + b + 0] = (vel[b + 0] + ex) * vs + g_cons4[p + 0] / cnt;
    out[2 * N3 + b + 1] = (vel[b + 1] + ey) * vs + g_cons4[p + 1] / cnt;
    out[2 * N3 + b + 2] = (vel[b + 2] + ez) * vs + g_cons4[p + 2] / cnt;
}

extern "C" void kernel_launch(void* const* d_in, const int* in_sizes, int n_in,
                              void* d_out, int out_size) {
    const int* ei       = (const int*)d_in[0];
    const float* latent = (const float*)d_in[1];
    const float* vel    = (const float*)d_in[2];
    const float* ef     = (const float*)d_in[3];
    const float* et     = (const float*)d_in[4];
    const float* ec     = (const float*)d_in[5];

    const int E = in_sizes[0] / 2;
    const int N = in_sizes[1] / LATENT;

    PrepArgs pa;
    FusedArgs fa;
    fa.latent = latent;
    for (int m = 0; m < 4; m++) {
        pa.W1[m] = (const float*)d_in[6 + 4 * m + 0];
        fa.b1[m] = (const float*)d_in[6 + 4 * m + 1];
        fa.W2[m] = (const float*)d_in[6 + 4 * m + 2];
        fa.b2[m] = (const float*)d_in[6 + 4 * m + 3];
    }
    fa.recv = ei + E;
    fa.ef = ef;
    fa.et = et;
    fa.ec = ec;
    fa.N = N;
    fa.E = E;
    const int NB = (N + TN - 1) / TN;
    fa.NB = NB;

    (void)cudaFuncSetAttribute(fused_kernel,
                               cudaFuncAttributeMaxDynamicSharedMemorySize,
                               SMEM_BYTES);

    zero_kernel<<<(N * 4 + 255) / 256, 256>>>(N);
    prep_w_kernel<<<(4 * 8192 + 255) / 256, 256>>>(pa);
    fused_kernel<<<NB * 3, 256, SMEM_BYTES>>>(fa);
    combine_kernel<<<(N + 255) / 256, 256>>>(vel, (float*)d_out, N);
}